// round 13
// baseline (speedup 1.0000x reference)
#include <cuda_runtime.h>
#include <cstdint>

// Problem constants
#define BB 64
#define HH 1024
#define II 512
#define MIN_TAU 1e-3f
#define LOG2E 1.4426950408889634f

// Tiling: 256 resident CTAs (single wave on 148 SMs x 2 CTAs).
// CTA = fixed o-group of 8 rows x 32 b-iterations.
// 8 consumer warps + 1 dedicated producer warp = 288 threads.
#define OW 8
#define NWARPS 9
#define BITERS 32
#define OGROUPS (HH / OW)       // 128
#define HALVES (BB / BITERS)    // 2
#define STAGES 3

// SMEM layout (dynamic) — stage = [gA 16KB][gB 16KB][h 4KB].
#define GH_BYTES (4 * HH * 4)            // 16384: half the gumbel tile (4 rows)
#define H_BYTES (HH * 4)                 // 4096
#define STAGE_BYTES (2 * GH_BYTES + H_BYTES)  // 36864
// Barriers per stage: fullA, fullB, fullH, emptyA, emptyB, emptyH (6 x 8B)
#define BAR_OFF (STAGES * STAGE_BYTES)
#define SMEM_BYTES (BAR_OFF + STAGES * 6 * 8)  // 110736 -> 2 CTAs/SM

static __device__ __forceinline__ uint32_t s2u(const void* p) {
    uint32_t a;
    asm("{ .reg .u64 t; cvta.to.shared.u64 t, %1; cvt.u32.u64 %0, t; }"
        : "=r"(a) : "l"(p));
    return a;
}

static __device__ __forceinline__ void mbar_init(uint32_t mbar, uint32_t cnt) {
    asm volatile("mbarrier.init.shared.b64 [%0], %1;" :: "r"(mbar), "r"(cnt) : "memory");
}

static __device__ __forceinline__ void mbar_expect_tx(uint32_t mbar, uint32_t bytes) {
    asm volatile("mbarrier.arrive.expect_tx.shared.b64 _, [%0], %1;"
                 :: "r"(mbar), "r"(bytes) : "memory");
}

static __device__ __forceinline__ void mbar_arrive(uint32_t mbar) {
    asm volatile("mbarrier.arrive.release.cta.shared::cta.b64 _, [%0];"
                 :: "r"(mbar) : "memory");
}

static __device__ __forceinline__ void mbar_wait(uint32_t mbar, uint32_t parity) {
    uint32_t done;
    asm volatile(
        "{\n\t.reg .pred p;\n\t"
        "mbarrier.try_wait.parity.acquire.cta.shared::cta.b64 p, [%1], %2;\n\t"
        "selp.b32 %0, 1, 0, p;\n\t}"
        : "=r"(done) : "r"(mbar), "r"(parity) : "memory");
    if (!done) {
        asm volatile(
            "{\n\t.reg .pred P1;\n\t"
            "WL_%=:\n\t"
            "mbarrier.try_wait.parity.acquire.cta.shared::cta.b64 P1, [%0], %1, 0x989680;\n\t"
            "@P1 bra.uni WD_%=;\n\t"
            "bra.uni WL_%=;\n\t"
            "WD_%=:\n\t}"
            :: "r"(mbar), "r"(parity) : "memory");
    }
}

static __device__ __forceinline__ void bulk_copy(uint32_t dst_smem, const void* src,
                                                 uint32_t bytes, uint32_t mbar) {
    asm volatile(
        "cp.async.bulk.shared::cta.global.mbarrier::complete_tx::bytes [%0], [%1], %2, [%3];"
        :: "r"(dst_smem), "l"(src), "r"(bytes), "r"(mbar) : "memory");
}

static __device__ __forceinline__ void fence_async_smem() {
    asm volatile("fence.proxy.async.shared::cta;" ::: "memory");
}

static __device__ __forceinline__ float ex2(float x) {
    float y;
    asm("ex2.approx.ftz.f32 %0, %1;" : "=f"(y) : "f"(x));
    return y;
}

// Fused ReservoirRNNCell step — warp-specialized TMA pipeline with SPLIT
// stage barriers:
//   grid = 256 CTAs (one wave at 2 CTAs/SM), 288 threads: warps 0-7 consume,
//   warp 8 produces. 3-stage ring; each fill = THREE copies with independent
//   barrier pairs:
//     copyH: 4KB h_prev[b,:]      (fullH / emptyH, 8 arrivals)
//     copyA: 16KB gumbel rows 0-3 (fullA / emptyA, 4 arrivals: warps 0-3)
//     copyB: 16KB gumbel rows 4-7 (fullB / emptyB, 4 arrivals: warps 4-7)
//   Consumer w waits fullH + full{A|B} only: unblocks on 20KB instead of the
//   whole 36KB stage, and the DRAM-heavy 16KB copies are gated by 4-warp
//   slowest-sets instead of 8. 16KB copies stay well above the 4KB
//   bad-granularity regime (R4/R10). Addressing identical to R9.
// h_prev MUST ride the TMA payload (LDG in the consumer loop drained the
// pipeline in R10/R11). Softmax without max-subtraction is safe: logits
// bounded (~18.5); validated rel_err 3.4e-7 in R1-R12.
__global__ __launch_bounds__(288, 2) void reservoir_cell_kernel(
    const float* __restrict__ x_t,         // (B, I)
    const float* __restrict__ h_prev,      // (B, H)
    const float* __restrict__ W_ih,        // (H, I)
    const float* __restrict__ b_ih,        // (H,)
    const float* __restrict__ W_hh,        // (H, H)
    const float* __restrict__ temperature, // scalar
    const float* __restrict__ gumbel,      // (B, H, H)
    float* __restrict__ out)               // (B, H)
{
    extern __shared__ float smem[];
    const uint32_t smem_u = s2u(smem);
    const uint32_t barb = smem_u + BAR_OFF;
    // barrier addressing: stage st, slot k (0=fullA,1=fullB,2=fullH,
    //                                       3=emptyA,4=emptyB,5=emptyH)
#define BAR(st, k) (barb + 8u * ((st) * 6 + (k)))

    const int og   = blockIdx.x & (OGROUPS - 1);   // 0..127
    const int half = blockIdx.x >> 7;              // 0..1
    const int b0 = half * BITERS;
    const int o0 = og * OW;

    const int tid  = threadIdx.x;
    const int w    = tid >> 5;
    const int lane = tid & 31;

    // ---- init barriers ----
    if (tid == 0) {
#pragma unroll
        for (int j = 0; j < STAGES; ++j) {
            mbar_init(BAR(j, 0), 1);   // fullA (tx)
            mbar_init(BAR(j, 1), 1);   // fullB (tx)
            mbar_init(BAR(j, 2), 1);   // fullH (tx)
            mbar_init(BAR(j, 3), 4);   // emptyA: warps 0-3
            mbar_init(BAR(j, 4), 4);   // emptyB: warps 4-7
            mbar_init(BAR(j, 5), OW);  // emptyH: all 8 consumer warps
        }
    }
    __syncthreads();   // the ONLY block-wide sync

    // ================= PRODUCER WARP (w == 8) =================
    if (w == 8) {
        if (lane == 0) {
            int st = 0, rnd = 0;
            for (int f = 0; f < BITERS; ++f) {
                const int b = b0 + f;
                const float* gsrc = gumbel + ((size_t)b * HH + o0) * HH;
                const float* hsrc = h_prev + (size_t)b * HH;
                const uint32_t dst = smem_u + st * STAGE_BYTES;
                const uint32_t ep = (rnd - 1) & 1;

                // h first (L2-resident source -> completes fast)
                if (rnd >= 1) { mbar_wait(BAR(st, 5), ep); fence_async_smem(); }
                mbar_expect_tx(BAR(st, 2), H_BYTES);
                bulk_copy(dst + 2 * GH_BYTES, hsrc, H_BYTES, BAR(st, 2));

                // gumbel half A: rows 0-3 (16KB contiguous)
                if (rnd >= 1) { mbar_wait(BAR(st, 3), ep); fence_async_smem(); }
                mbar_expect_tx(BAR(st, 0), GH_BYTES);
                bulk_copy(dst, gsrc, GH_BYTES, BAR(st, 0));

                // gumbel half B: rows 4-7
                if (rnd >= 1) { mbar_wait(BAR(st, 4), ep); fence_async_smem(); }
                mbar_expect_tx(BAR(st, 1), GH_BYTES);
                bulk_copy(dst + GH_BYTES, gsrc + 4 * HH, GH_BYTES, BAR(st, 1));

                if (++st == STAGES) { st = 0; ++rnd; }
            }
        }
        return;
    }

    // ================= CONSUMER WARPS (w == 0..7) =================
    const int o = o0 + w;
    const int grp = w >> 2;            // 0: half A, 1: half B
    const uint32_t full_g  = 0u + grp; // slot 0 or 1
    const uint32_t empty_g = 3u + grp; // slot 3 or 4

    // per-warp constants, loaded ONCE per 32 tiles (overlaps prologue TMA)
    const float inv_tau_l2e = LOG2E / fmaxf(temperature[0], MIN_TAU);
    const float bias = b_ih[o];

    const float4* __restrict__ whr = reinterpret_cast<const float4*>(W_hh + (size_t)o * HH);
    float4 wp[8];
#pragma unroll
    for (int k = 0; k < 8; ++k) {
        float4 v = whr[lane + 32 * k];
        v.x *= inv_tau_l2e; v.y *= inv_tau_l2e;
        v.z *= inv_tau_l2e; v.w *= inv_tau_l2e;
        wp[k] = v;
    }
    const float4* __restrict__ wir = reinterpret_cast<const float4*>(W_ih + (size_t)o * II);
    float4 wih[4];
#pragma unroll
    for (int k = 0; k < 4; ++k) wih[k] = wir[lane + 32 * k];

    int st = 0;
    int parity = 0;   // round parity: r = i/STAGES, parity = r&1
    for (int i = 0; i < BITERS; ++i) {
        const int b = b0 + i;

        // input contribution (register-cached W_ih) — overlaps the waits
        const float4* __restrict__ xr =
            reinterpret_cast<const float4*>(x_t + (size_t)b * II);
        float ic = 0.0f;
#pragma unroll
        for (int k = 0; k < 4; ++k) {
            const float4 xv = xr[lane + 32 * k];
            ic = fmaf(xv.x, wih[k].x, ic);
            ic = fmaf(xv.y, wih[k].y, ic);
            ic = fmaf(xv.z, wih[k].z, ic);
            ic = fmaf(xv.w, wih[k].w, ic);
        }

        // wait only for OUR half + the h row (20KB, not the whole 36KB)
        mbar_wait(BAR(st, 2), parity);       // fullH
        mbar_wait(BAR(st, full_g), parity);  // fullA or fullB

        const float4* __restrict__ gs = reinterpret_cast<const float4*>(
            smem + (size_t)st * (STAGE_BYTES / 4) + (size_t)w * HH);
        const float4* __restrict__ hs = reinterpret_cast<const float4*>(
            smem + (size_t)st * (STAGE_BYTES / 4) + 2 * (GH_BYTES / 4));

        float s = 0.0f, t = 0.0f;
#pragma unroll
        for (int k = 0; k < 8; ++k) {
            const int idx = lane + 32 * k;
            const float4 g = gs[idx];
            const float4 h = hs[idx];
            float e;
            e = ex2(fmaf(g.x, LOG2E, wp[k].x)); s += e; t = fmaf(e, h.x, t);
            e = ex2(fmaf(g.y, LOG2E, wp[k].y)); s += e; t = fmaf(e, h.y, t);
            e = ex2(fmaf(g.z, LOG2E, wp[k].z)); s += e; t = fmaf(e, h.z, t);
            e = ex2(fmaf(g.w, LOG2E, wp[k].w)); s += e; t = fmaf(e, h.w, t);
        }

        // consumed into registers: release our half + the h barrier.
        __syncwarp();
        if (lane == 0) {
            mbar_arrive(BAR(st, empty_g));
            mbar_arrive(BAR(st, 5));
        }

        // warp reductions + output (overlaps the producer's refill)
#pragma unroll
        for (int off = 16; off > 0; off >>= 1) {
            s  += __shfl_xor_sync(0xffffffffu, s,  off);
            t  += __shfl_xor_sync(0xffffffffu, t,  off);
            ic += __shfl_xor_sync(0xffffffffu, ic, off);
        }
        if (lane == 0) {
            out[(size_t)b * HH + o] = tanhf(ic + bias + t / s);
        }

        if (++st == STAGES) { st = 0; parity ^= 1; }
    }
#undef BAR
}

extern "C" void kernel_launch(void* const* d_in, const int* in_sizes, int n_in,
                              void* d_out, int out_size) {
    // metadata order: x_t, h_prev, W_ih, b_ih, W_hh, temperature, gumbel_noise
    const float* x_t    = (const float*)d_in[0];
    const float* h_prev = (const float*)d_in[1];
    const float* W_ih   = (const float*)d_in[2];
    const float* b_ih   = (const float*)d_in[3];
    const float* W_hh   = (const float*)d_in[4];
    const float* temp   = (const float*)d_in[5];
    const float* gum    = (const float*)d_in[6];
    float* out = (float*)d_out;

    static bool attr_set = false;
    if (!attr_set) {
        cudaFuncSetAttribute(reservoir_cell_kernel,
                             cudaFuncAttributeMaxDynamicSharedMemorySize, SMEM_BYTES);
        attr_set = true;
    }

    dim3 grid(OGROUPS * HALVES);   // 128 * 2 = 256 CTAs: one resident wave
    dim3 block(NWARPS * 32);       // 288 threads: 8 consumer + 1 producer warp
    reservoir_cell_kernel<<<grid, block, SMEM_BYTES>>>(
        x_t, h_prev, W_ih, b_ih, W_hh, temp, gum, out);
}

// round 14
// speedup vs baseline: 1.3049x; 1.3049x over previous
#include <cuda_runtime.h>
#include <cstdint>

// Problem constants
#define BB 64
#define HH 1024
#define II 512
#define MIN_TAU 1e-3f
#define LOG2E 1.4426950408889634f

// 296 CTAs = exactly 2 resident CTAs on every one of 148 SMs.
// CTA = fixed o-group (og = bid % 128); b-tiles pulled dynamically from a
// per-og atomic pool (64 tiles, CHUNK=4 grabs) so all 296 pipelines stay fed
// and work self-balances across og siblings (2-3 CTAs per og).
#define OW 8
#define NWARPS 9
#define OGROUPS (HH / OW)   // 128
#define NCTAS 296
#define STAGES 3
#define CHUNK 4

// SMEM layout (dynamic) — R9 proven stage: 32KB gumbel + 4KB h_prev.
#define G_BYTES (OW * HH * 4)            // 32768
#define H_BYTES (HH * 4)                 // 4096
#define STAGE_BYTES (G_BYTES + H_BYTES)  // 36864
#define FULL_OFF (STAGES * STAGE_BYTES)  // 110592
#define EMPTY_OFF (FULL_OFF + STAGES * 8)
#define BIDX_OFF (EMPTY_OFF + STAGES * 8)      // int per stage: tile's b (or -1)
#define SMEM_BYTES (BIDX_OFF + STAGES * 4)     // 110652 -> 2 CTAs/SM

__device__ int g_ctr[OGROUPS];   // per-og tile pool counters (reset per launch)

static __device__ __forceinline__ uint32_t s2u(const void* p) {
    uint32_t a;
    asm("{ .reg .u64 t; cvta.to.shared.u64 t, %1; cvt.u32.u64 %0, t; }"
        : "=r"(a) : "l"(p));
    return a;
}

static __device__ __forceinline__ void mbar_init(uint32_t mbar, uint32_t cnt) {
    asm volatile("mbarrier.init.shared.b64 [%0], %1;" :: "r"(mbar), "r"(cnt) : "memory");
}

static __device__ __forceinline__ void mbar_expect_tx(uint32_t mbar, uint32_t bytes) {
    asm volatile("mbarrier.arrive.expect_tx.shared.b64 _, [%0], %1;"
                 :: "r"(mbar), "r"(bytes) : "memory");
}

static __device__ __forceinline__ void mbar_arrive(uint32_t mbar) {
    asm volatile("mbarrier.arrive.release.cta.shared::cta.b64 _, [%0];"
                 :: "r"(mbar) : "memory");
}

static __device__ __forceinline__ void mbar_wait(uint32_t mbar, uint32_t parity) {
    uint32_t done;
    asm volatile(
        "{\n\t.reg .pred p;\n\t"
        "mbarrier.try_wait.parity.acquire.cta.shared::cta.b64 p, [%1], %2;\n\t"
        "selp.b32 %0, 1, 0, p;\n\t}"
        : "=r"(done) : "r"(mbar), "r"(parity) : "memory");
    if (!done) {
        asm volatile(
            "{\n\t.reg .pred P1;\n\t"
            "WL_%=:\n\t"
            "mbarrier.try_wait.parity.acquire.cta.shared::cta.b64 P1, [%0], %1, 0x989680;\n\t"
            "@P1 bra.uni WD_%=;\n\t"
            "bra.uni WL_%=;\n\t"
            "WD_%=:\n\t}"
            :: "r"(mbar), "r"(parity) : "memory");
    }
}

static __device__ __forceinline__ void bulk_copy(uint32_t dst_smem, const void* src,
                                                 uint32_t bytes, uint32_t mbar) {
    asm volatile(
        "cp.async.bulk.shared::cta.global.mbarrier::complete_tx::bytes [%0], [%1], %2, [%3];"
        :: "r"(dst_smem), "l"(src), "r"(bytes), "r"(mbar) : "memory");
}

static __device__ __forceinline__ void fence_async_smem() {
    asm volatile("fence.proxy.async.shared::cta;" ::: "memory");
}

static __device__ __forceinline__ float ex2(float x) {
    float y;
    asm("ex2.approx.ftz.f32 %0, %1;" : "=f"(y) : "f"(x));
    return y;
}

// Tiny prologue kernel: reset the per-og pool counters (same graph capture,
// same stream -> serialized before the main kernel).
__global__ void reset_counters_kernel() {
    if (threadIdx.x < OGROUPS) g_ctr[threadIdx.x] = 0;
}

// Fused ReservoirRNNCell step — R9 pipeline (one 36KB bulk copy per stage,
// 3-stage ring, dedicated producer warp, per-stage full/empty barriers; the
// proven optimum for the handshake) with a DYNAMIC per-og tile scheduler so
// all 296 resident CTA-pipelines (exactly 2/SM) stay fed:
//   producer: grab CHUNK b-tiles via atomicAdd(g_ctr[og]); per tile: wait
//   empty (round>=1) -> fence -> STS b into bidx[st] -> expect_tx (the
//   arrive-release orders the STS for consumers) -> one 32KB gumbel copy +
//   4KB h_prev copy. Pool empty -> STS -1 + plain release-arrive (flips the
//   full barrier with no tx) -> exit.
//   consumers: wait full (acquire) -> read b -> consume -> arrive empty ->
//   reduce/store; exit on b < 0.
// Any og's tile is computed identically by whichever sibling grabs it ->
// output deterministic. h_prev rides the TMA payload (LDG in the consumer
// loop drained the pipeline in R10/R11). Softmax without max-subtraction is
// safe: logits bounded (~18.5); validated rel_err 3.4e-7 in R1-R13.
__global__ __launch_bounds__(288, 2) void reservoir_cell_kernel(
    const float* __restrict__ x_t,         // (B, I)
    const float* __restrict__ h_prev,      // (B, H)
    const float* __restrict__ W_ih,        // (H, I)
    const float* __restrict__ b_ih,        // (H,)
    const float* __restrict__ W_hh,        // (H, H)
    const float* __restrict__ temperature, // scalar
    const float* __restrict__ gumbel,      // (B, H, H)
    float* __restrict__ out)               // (B, H)
{
    extern __shared__ float smem[];
    const uint32_t smem_u = s2u(smem);
    const uint32_t fullb  = smem_u + FULL_OFF;
    const uint32_t emptyb = smem_u + EMPTY_OFF;
    int* __restrict__ bidx = reinterpret_cast<int*>(
        reinterpret_cast<char*>(smem) + BIDX_OFF);

    const int og = blockIdx.x & (OGROUPS - 1);   // bid % 128 (296 < 2*256)
    const int o0 = og * OW;

    const int tid  = threadIdx.x;
    const int w    = tid >> 5;
    const int lane = tid & 31;

    // ---- init barriers ----
    if (tid == 0) {
#pragma unroll
        for (int j = 0; j < STAGES; ++j) {
            mbar_init(fullb + 8u * j, 1);
            mbar_init(emptyb + 8u * j, OW);   // one arrive per consumer warp
        }
    }
    __syncthreads();   // the ONLY block-wide sync

    // ================= PRODUCER WARP (w == 8) =================
    if (w == 8) {
        if (lane == 0) {
            int st = 0, rnd = 0, rem = 0, bcur = 0;
            for (;;) {
                if (rem == 0) {
                    const int p = atomicAdd(&g_ctr[og], CHUNK);
                    if (p >= BB) {
                        // pool empty: sentinel on the current stage
                        if (rnd >= 1) {
                            mbar_wait(emptyb + 8u * st, (rnd - 1) & 1);
                            fence_async_smem();
                        }
                        bidx[st] = -1;
                        mbar_arrive(fullb + 8u * st);  // release: flips (no tx)
                        break;
                    }
                    bcur = p;
                    rem = CHUNK;
                }
                if (rnd >= 1) {
                    mbar_wait(emptyb + 8u * st, (rnd - 1) & 1);
                    fence_async_smem();
                }
                bidx[st] = bcur;   // ordered by the expect_tx arrive-release
                const uint32_t mb = fullb + 8u * st;
                mbar_expect_tx(mb, STAGE_BYTES);
                const float* gsrc = gumbel + ((size_t)bcur * HH + o0) * HH;
                bulk_copy(smem_u + st * STAGE_BYTES, gsrc, G_BYTES, mb);
                const float* hsrc = h_prev + (size_t)bcur * HH;
                bulk_copy(smem_u + st * STAGE_BYTES + G_BYTES, hsrc, H_BYTES, mb);
                --rem; ++bcur;
                if (++st == STAGES) { st = 0; ++rnd; }
            }
        }
        return;
    }

    // ================= CONSUMER WARPS (w == 0..7) =================
    const int o = o0 + w;

    // per-warp constants, loaded ONCE (og fixed per CTA; overlaps prologue)
    const float inv_tau_l2e = LOG2E / fmaxf(temperature[0], MIN_TAU);
    const float bias = b_ih[o];

    const float4* __restrict__ whr = reinterpret_cast<const float4*>(W_hh + (size_t)o * HH);
    float4 wp[8];
#pragma unroll
    for (int k = 0; k < 8; ++k) {
        float4 v = whr[lane + 32 * k];
        v.x *= inv_tau_l2e; v.y *= inv_tau_l2e;
        v.z *= inv_tau_l2e; v.w *= inv_tau_l2e;
        wp[k] = v;
    }
    const float4* __restrict__ wir = reinterpret_cast<const float4*>(W_ih + (size_t)o * II);
    float4 wih[4];
#pragma unroll
    for (int k = 0; k < 4; ++k) wih[k] = wir[lane + 32 * k];

    int st = 0;
    int parity = 0;   // stage st's k-th use has parity k&1
    for (;;) {
        mbar_wait(fullb + 8u * st, parity);
        const int b = bidx[st];   // visible via acquire (producer released it)
        if (b < 0) break;

        // input contribution: x_t row LDG (L2-resident) issues here; its
        // latency hides under the gumbel LDS/MUFU chain below (ic is only
        // consumed at the reduction).
        const float4* __restrict__ xr =
            reinterpret_cast<const float4*>(x_t + (size_t)b * II);
        float ic = 0.0f;
#pragma unroll
        for (int k = 0; k < 4; ++k) {
            const float4 xv = xr[lane + 32 * k];
            ic = fmaf(xv.x, wih[k].x, ic);
            ic = fmaf(xv.y, wih[k].y, ic);
            ic = fmaf(xv.z, wih[k].z, ic);
            ic = fmaf(xv.w, wih[k].w, ic);
        }

        const float4* __restrict__ gs = reinterpret_cast<const float4*>(
            smem + (size_t)st * (STAGE_BYTES / 4) + (size_t)w * HH);
        const float4* __restrict__ hs = reinterpret_cast<const float4*>(
            smem + (size_t)st * (STAGE_BYTES / 4) + G_BYTES / 4);

        float s = 0.0f, t = 0.0f;
#pragma unroll
        for (int k = 0; k < 8; ++k) {
            const int idx = lane + 32 * k;
            const float4 g = gs[idx];
            const float4 h = hs[idx];
            float e;
            e = ex2(fmaf(g.x, LOG2E, wp[k].x)); s += e; t = fmaf(e, h.x, t);
            e = ex2(fmaf(g.y, LOG2E, wp[k].y)); s += e; t = fmaf(e, h.y, t);
            e = ex2(fmaf(g.z, LOG2E, wp[k].z)); s += e; t = fmaf(e, h.z, t);
            e = ex2(fmaf(g.w, LOG2E, wp[k].w)); s += e; t = fmaf(e, h.w, t);
        }

        // stage consumed into registers: signal the producer, move on.
        __syncwarp();
        if (lane == 0) mbar_arrive(emptyb + 8u * st);

        // warp reductions + output (overlaps the producer's refill)
#pragma unroll
        for (int off = 16; off > 0; off >>= 1) {
            s  += __shfl_xor_sync(0xffffffffu, s,  off);
            t  += __shfl_xor_sync(0xffffffffu, t,  off);
            ic += __shfl_xor_sync(0xffffffffu, ic, off);
        }
        if (lane == 0) {
            out[(size_t)b * HH + o] = tanhf(ic + bias + t / s);
        }

        if (++st == STAGES) { st = 0; parity ^= 1; }
    }
}

extern "C" void kernel_launch(void* const* d_in, const int* in_sizes, int n_in,
                              void* d_out, int out_size) {
    // metadata order: x_t, h_prev, W_ih, b_ih, W_hh, temperature, gumbel_noise
    const float* x_t    = (const float*)d_in[0];
    const float* h_prev = (const float*)d_in[1];
    const float* W_ih   = (const float*)d_in[2];
    const float* b_ih   = (const float*)d_in[3];
    const float* W_hh   = (const float*)d_in[4];
    const float* temp   = (const float*)d_in[5];
    const float* gum    = (const float*)d_in[6];
    float* out = (float*)d_out;

    static bool attr_set = false;
    if (!attr_set) {
        cudaFuncSetAttribute(reservoir_cell_kernel,
                             cudaFuncAttributeMaxDynamicSharedMemorySize, SMEM_BYTES);
        attr_set = true;
    }

    // 1) reset the per-og pools (same stream -> ordered before main kernel)
    reset_counters_kernel<<<1, 128>>>();
    // 2) main kernel: 296 CTAs = exactly 2 per SM
    dim3 grid(NCTAS);
    dim3 block(NWARPS * 32);       // 288 threads: 8 consumer + 1 producer warp
    reservoir_cell_kernel<<<grid, block, SMEM_BYTES>>>(
        x_t, h_prev, W_ih, b_ih, W_hh, temp, gum, out);
}

// round 15
// speedup vs baseline: 1.3645x; 1.0456x over previous
#include <cuda_runtime.h>
#include <cstdint>

// Problem constants
#define BB 64
#define HH 1024
#define II 512
#define MIN_TAU 1e-3f
#define LOG2E 1.4426950408889634f

// 296 CTAs = exactly 2 resident CTAs on every one of 148 SMs.
// CTA = fixed o-group (og = bid % 128); b-tiles pulled dynamically from a
// per-og atomic pool (64 tiles, CHUNK=2 grabs). ogs 0..39 have 3 sibling
// CTAs, ogs 40..127 have 2.
#define OW 8
#define NWARPS 9
#define OGROUPS (HH / OW)   // 128
#define NCTAS 296
#define STAGES 3
#define CHUNK 2

// SMEM layout (dynamic) — R9-proven stage: 32KB gumbel + 4KB h_prev.
#define G_BYTES (OW * HH * 4)            // 32768
#define H_BYTES (HH * 4)                 // 4096
#define STAGE_BYTES (G_BYTES + H_BYTES)  // 36864
#define FULL_OFF (STAGES * STAGE_BYTES)  // 110592
#define EMPTY_OFF (FULL_OFF + STAGES * 8)
#define BIDX_OFF (EMPTY_OFF + STAGES * 8)      // int per stage: tile's b (or -1)
#define SMEM_BYTES (BIDX_OFF + STAGES * 4)     // 110652 -> 2 CTAs/SM

// Pool state. Zero at module load; the LAST sibling of each og restores both
// to zero before exiting, so every graph replay starts from a clean state —
// no prologue reset kernel needed.
__device__ int g_ctr[OGROUPS];
__device__ int g_done[OGROUPS];

static __device__ __forceinline__ uint32_t s2u(const void* p) {
    uint32_t a;
    asm("{ .reg .u64 t; cvta.to.shared.u64 t, %1; cvt.u32.u64 %0, t; }"
        : "=r"(a) : "l"(p));
    return a;
}

static __device__ __forceinline__ void mbar_init(uint32_t mbar, uint32_t cnt) {
    asm volatile("mbarrier.init.shared.b64 [%0], %1;" :: "r"(mbar), "r"(cnt) : "memory");
}

static __device__ __forceinline__ void mbar_expect_tx(uint32_t mbar, uint32_t bytes) {
    asm volatile("mbarrier.arrive.expect_tx.shared.b64 _, [%0], %1;"
                 :: "r"(mbar), "r"(bytes) : "memory");
}

static __device__ __forceinline__ void mbar_arrive(uint32_t mbar) {
    asm volatile("mbarrier.arrive.release.cta.shared::cta.b64 _, [%0];"
                 :: "r"(mbar) : "memory");
}

static __device__ __forceinline__ void mbar_wait(uint32_t mbar, uint32_t parity) {
    uint32_t done;
    asm volatile(
        "{\n\t.reg .pred p;\n\t"
        "mbarrier.try_wait.parity.acquire.cta.shared::cta.b64 p, [%1], %2;\n\t"
        "selp.b32 %0, 1, 0, p;\n\t}"
        : "=r"(done) : "r"(mbar), "r"(parity) : "memory");
    if (!done) {
        asm volatile(
            "{\n\t.reg .pred P1;\n\t"
            "WL_%=:\n\t"
            "mbarrier.try_wait.parity.acquire.cta.shared::cta.b64 P1, [%0], %1, 0x989680;\n\t"
            "@P1 bra.uni WD_%=;\n\t"
            "bra.uni WL_%=;\n\t"
            "WD_%=:\n\t}"
            :: "r"(mbar), "r"(parity) : "memory");
    }
}

static __device__ __forceinline__ void bulk_copy(uint32_t dst_smem, const void* src,
                                                 uint32_t bytes, uint32_t mbar) {
    asm volatile(
        "cp.async.bulk.shared::cta.global.mbarrier::complete_tx::bytes [%0], [%1], %2, [%3];"
        :: "r"(dst_smem), "l"(src), "r"(bytes), "r"(mbar) : "memory");
}

static __device__ __forceinline__ void fence_async_smem() {
    asm volatile("fence.proxy.async.shared::cta;" ::: "memory");
}

static __device__ __forceinline__ float ex2(float x) {
    float y;
    asm("ex2.approx.ftz.f32 %0, %1;" : "=f"(y) : "f"(x));
    return y;
}

// Fused ReservoirRNNCell step — R14 structure (R9 pipeline + dynamic per-og
// tile scheduler across 296 resident CTA-pipelines) with two changes:
//   1) SELF-RESTORING pools: each producer, after its failing grab (it never
//      touches g_ctr again), does threadfence + atomicAdd(g_done[og]); the
//      LAST sibling (nsib = 3 for og<40 else 2) zeroes g_ctr/g_done. Every
//      sibling's failing grab strictly precedes its done-increment, so the
//      reset is ordered after all pool accesses. The prologue reset kernel
//      (one serialized graph node) is deleted.
//   2) CHUNK 4 -> 2: halves per-og ragged-end imbalance; the extra atomics
//      sit in the producer's ample slack.
// Pipeline per CTA: 3-stage ring, ONE 32KB gumbel bulk copy + 4KB h_prev
// per stage (proven optimal granularity; 4KB/16KB splits regressed), per-
// stage full (tx) / empty (8 arrivals) barriers, dedicated producer warp,
// consumers never wait on each other. h_prev rides the TMA payload (consumer
// -loop LDG of it drained the pipeline in R10/R11). Softmax without max-
// subtraction is safe: logits bounded (~18.5); rel_err 3.4e-7 across rounds.
__global__ __launch_bounds__(288, 2) void reservoir_cell_kernel(
    const float* __restrict__ x_t,         // (B, I)
    const float* __restrict__ h_prev,      // (B, H)
    const float* __restrict__ W_ih,        // (H, I)
    const float* __restrict__ b_ih,        // (H,)
    const float* __restrict__ W_hh,        // (H, H)
    const float* __restrict__ temperature, // scalar
    const float* __restrict__ gumbel,      // (B, H, H)
    float* __restrict__ out)               // (B, H)
{
    extern __shared__ float smem[];
    const uint32_t smem_u = s2u(smem);
    const uint32_t fullb  = smem_u + FULL_OFF;
    const uint32_t emptyb = smem_u + EMPTY_OFF;
    int* __restrict__ bidx = reinterpret_cast<int*>(
        reinterpret_cast<char*>(smem) + BIDX_OFF);

    const int og = blockIdx.x & (OGROUPS - 1);   // bid % 128
    const int o0 = og * OW;

    const int tid  = threadIdx.x;
    const int w    = tid >> 5;
    const int lane = tid & 31;

    // ---- init barriers ----
    if (tid == 0) {
#pragma unroll
        for (int j = 0; j < STAGES; ++j) {
            mbar_init(fullb + 8u * j, 1);
            mbar_init(emptyb + 8u * j, OW);   // one arrive per consumer warp
        }
    }
    __syncthreads();   // the ONLY block-wide sync

    // ================= PRODUCER WARP (w == 8) =================
    if (w == 8) {
        if (lane == 0) {
            int st = 0, rnd = 0, rem = 0, bcur = 0;
            for (;;) {
                if (rem == 0) {
                    const int p = atomicAdd(&g_ctr[og], CHUNK);
                    if (p >= BB) {
                        // pool empty: sentinel on the current stage
                        if (rnd >= 1) {
                            mbar_wait(emptyb + 8u * st, (rnd - 1) & 1);
                            fence_async_smem();
                        }
                        bidx[st] = -1;
                        mbar_arrive(fullb + 8u * st);  // release: flips (no tx)

                        // ---- pool restore (replaces the prologue kernel) ----
                        __threadfence();  // order our g_ctr add before g_done
                        const int nsib = (og < (NCTAS - 2 * OGROUPS)) ? 3 : 2;
                        const int d = atomicAdd(&g_done[og], 1);
                        if (d == nsib - 1) {   // last sibling of this og
                            atomicExch(&g_ctr[og], 0);
                            atomicExch(&g_done[og], 0);
                        }
                        break;
                    }
                    bcur = p;
                    rem = CHUNK;
                }
                if (rnd >= 1) {
                    mbar_wait(emptyb + 8u * st, (rnd - 1) & 1);
                    fence_async_smem();
                }
                bidx[st] = bcur;   // ordered by the expect_tx arrive-release
                const uint32_t mb = fullb + 8u * st;
                mbar_expect_tx(mb, STAGE_BYTES);
                const float* gsrc = gumbel + ((size_t)bcur * HH + o0) * HH;
                bulk_copy(smem_u + st * STAGE_BYTES, gsrc, G_BYTES, mb);
                const float* hsrc = h_prev + (size_t)bcur * HH;
                bulk_copy(smem_u + st * STAGE_BYTES + G_BYTES, hsrc, H_BYTES, mb);
                --rem; ++bcur;
                if (++st == STAGES) { st = 0; ++rnd; }
            }
        }
        return;
    }

    // ================= CONSUMER WARPS (w == 0..7) =================
    const int o = o0 + w;

    // per-warp constants, loaded ONCE (og fixed per CTA; overlaps prologue)
    const float inv_tau_l2e = LOG2E / fmaxf(temperature[0], MIN_TAU);
    const float bias = b_ih[o];

    const float4* __restrict__ whr = reinterpret_cast<const float4*>(W_hh + (size_t)o * HH);
    float4 wp[8];
#pragma unroll
    for (int k = 0; k < 8; ++k) {
        float4 v = whr[lane + 32 * k];
        v.x *= inv_tau_l2e; v.y *= inv_tau_l2e;
        v.z *= inv_tau_l2e; v.w *= inv_tau_l2e;
        wp[k] = v;
    }
    const float4* __restrict__ wir = reinterpret_cast<const float4*>(W_ih + (size_t)o * II);
    float4 wih[4];
#pragma unroll
    for (int k = 0; k < 4; ++k) wih[k] = wir[lane + 32 * k];

    int st = 0;
    int parity = 0;   // stage st's k-th use has parity k&1
    for (;;) {
        mbar_wait(fullb + 8u * st, parity);
        const int b = bidx[st];   // visible via acquire (producer released it)
        if (b < 0) break;

        // input contribution: x_t row LDG (L2-resident); latency hides under
        // the gumbel LDS/MUFU chain (ic only consumed at the reduction).
        const float4* __restrict__ xr =
            reinterpret_cast<const float4*>(x_t + (size_t)b * II);
        float ic = 0.0f;
#pragma unroll
        for (int k = 0; k < 4; ++k) {
            const float4 xv = xr[lane + 32 * k];
            ic = fmaf(xv.x, wih[k].x, ic);
            ic = fmaf(xv.y, wih[k].y, ic);
            ic = fmaf(xv.z, wih[k].z, ic);
            ic = fmaf(xv.w, wih[k].w, ic);
        }

        const float4* __restrict__ gs = reinterpret_cast<const float4*>(
            smem + (size_t)st * (STAGE_BYTES / 4) + (size_t)w * HH);
        const float4* __restrict__ hs = reinterpret_cast<const float4*>(
            smem + (size_t)st * (STAGE_BYTES / 4) + G_BYTES / 4);

        float s = 0.0f, t = 0.0f;
#pragma unroll
        for (int k = 0; k < 8; ++k) {
            const int idx = lane + 32 * k;
            const float4 g = gs[idx];
            const float4 h = hs[idx];
            float e;
            e = ex2(fmaf(g.x, LOG2E, wp[k].x)); s += e; t = fmaf(e, h.x, t);
            e = ex2(fmaf(g.y, LOG2E, wp[k].y)); s += e; t = fmaf(e, h.y, t);
            e = ex2(fmaf(g.z, LOG2E, wp[k].z)); s += e; t = fmaf(e, h.z, t);
            e = ex2(fmaf(g.w, LOG2E, wp[k].w)); s += e; t = fmaf(e, h.w, t);
        }

        // stage consumed into registers: signal the producer, move on.
        __syncwarp();
        if (lane == 0) mbar_arrive(emptyb + 8u * st);

        // warp reductions + output (overlaps the producer's refill)
#pragma unroll
        for (int off = 16; off > 0; off >>= 1) {
            s  += __shfl_xor_sync(0xffffffffu, s,  off);
            t  += __shfl_xor_sync(0xffffffffu, t,  off);
            ic += __shfl_xor_sync(0xffffffffu, ic, off);
        }
        if (lane == 0) {
            out[(size_t)b * HH + o] = tanhf(ic + bias + t / s);
        }

        if (++st == STAGES) { st = 0; parity ^= 1; }
    }
}

extern "C" void kernel_launch(void* const* d_in, const int* in_sizes, int n_in,
                              void* d_out, int out_size) {
    // metadata order: x_t, h_prev, W_ih, b_ih, W_hh, temperature, gumbel_noise
    const float* x_t    = (const float*)d_in[0];
    const float* h_prev = (const float*)d_in[1];
    const float* W_ih   = (const float*)d_in[2];
    const float* b_ih   = (const float*)d_in[3];
    const float* W_hh   = (const float*)d_in[4];
    const float* temp   = (const float*)d_in[5];
    const float* gum    = (const float*)d_in[6];
    float* out = (float*)d_out;

    static bool attr_set = false;
    if (!attr_set) {
        cudaFuncSetAttribute(reservoir_cell_kernel,
                             cudaFuncAttributeMaxDynamicSharedMemorySize, SMEM_BYTES);
        attr_set = true;
    }

    // Single kernel node: pools self-restore at the end of each launch.
    dim3 grid(NCTAS);              // 296 CTAs = exactly 2 per SM
    dim3 block(NWARPS * 32);       // 288 threads: 8 consumer + 1 producer warp
    reservoir_cell_kernel<<<grid, block, SMEM_BYTES>>>(
        x_t, h_prev, W_ih, b_ih, W_hh, temp, gum, out);
}